// round 5
// baseline (speedup 1.0000x reference)
#include <cuda_runtime.h>
#include <cuda_bf16.h>
#include <cstdint>

// ---------------- problem constants ----------------
#define Bsz 512
#define Wln 50
#define Tln 50
#define Hd  1024
#define Vb  1024
#define MVd 64
#define Ld  30
#define G4H 4096
#define SOS_INDEX 0
#define EOS_INDEX 1

// ---------------- scratch (device globals; no runtime alloc) ----------------
__device__ float d_c   [Bsz * Hd];
__device__ float d_mm  [Ld * Bsz];
__device__ float d_m   [Bsz];
__device__ float d_hA32[Bsz * Hd];
__device__ float d_hB32[Bsz * Hd];

#define ALN __align__(16)
__device__ ALN __nv_bfloat16 e_hi  [Vb * Hd],  e_lo  [Vb * Hd];
__device__ ALN __nv_bfloat16 wset_h[G4H * Hd], wset_l[G4H * Hd];
__device__ ALN __nv_bfloat16 wgen_h[G4H * Hd], wgen_l[G4H * Hd];
__device__ ALN __nv_bfloat16 wmi_h [G4H * MVd], wmi_l [G4H * MVd];
__device__ ALN __nv_bfloat16 wmh_h [G4H * Hd], wmh_l [G4H * Hd];
__device__ ALN __nv_bfloat16 wdi_h [G4H * Hd], wdi_l [G4H * Hd];
__device__ ALN __nv_bfloat16 wdh_h [G4H * Hd], wdh_l [G4H * Hd];
__device__ ALN __nv_bfloat16 wo_h  [Vb * Hd],  wo_l  [Vb * Hd];
__device__ ALN __nv_bfloat16 hA_hi [Bsz * Hd], hA_lo [Bsz * Hd];
__device__ ALN __nv_bfloat16 hB_hi [Bsz * Hd], hB_lo [Bsz * Hd];
__device__ ALN __nv_bfloat16 r_hi  [Bsz * Hd], r_lo  [Bsz * Hd];
__device__ ALN __nv_bfloat16 msg_hi[Ld * Bsz * MVd], msg_lo[Ld * Bsz * MVd];
__device__ ALN __nv_bfloat16 hall_hi[Tln * Bsz * Hd], hall_lo[Tln * Bsz * Hd];
__device__ float pb_set[G4H], pb_gen[G4H], pb_menc[G4H], pb_dec[G4H];

// ---------------- ptx helpers ----------------
__device__ __forceinline__ uint32_t smem_to_u32(const void* p) {
    uint32_t a;
    asm("{ .reg .u64 t; cvta.to.shared.u64 t, %1; cvt.u32.u64 %0, t; }" : "=r"(a) : "l"(p));
    return a;
}
#define CP_ASYNC16(dst, src) \
    asm volatile("cp.async.cg.shared.global [%0], [%1], 16;" :: "r"(dst), "l"(src))
#define CP_COMMIT() asm volatile("cp.async.commit_group;" ::: "memory")
#define CP_WAIT0()  asm volatile("cp.async.wait_group 0;" ::: "memory")
#define CP_WAIT1()  asm volatile("cp.async.wait_group 1;" ::: "memory")
#define LDSM4(r, a) \
    asm volatile("ldmatrix.sync.aligned.m8n8.x4.shared.b16 {%0,%1,%2,%3}, [%4];" \
        : "=r"((r)[0]), "=r"((r)[1]), "=r"((r)[2]), "=r"((r)[3]) : "r"(a))
#define SWZ(x) ((x) ^ (((x) >> 3) & 0x70))

__device__ __forceinline__ void mma16816(float* c, const uint32_t* a, const uint32_t* b)
{
    asm volatile(
        "mma.sync.aligned.m16n8k16.row.col.f32.bf16.bf16.f32 "
        "{%0,%1,%2,%3}, {%4,%5,%6,%7}, {%8,%9}, {%0,%1,%2,%3};\n"
        : "+f"(c[0]), "+f"(c[1]), "+f"(c[2]), "+f"(c[3])
        : "r"(a[0]), "r"(a[1]), "r"(a[2]), "r"(a[3]), "r"(b[0]), "r"(b[1]));
}

// ---------------- smem layout ----------------
#define SM_IDX    0          // 128 ints (gather indices)
#define SM_TILES  1024
#define TILE_B    16384      // one plane: 128 rows x 128B (64 bf16)
#define STAGE_B   (4 * TILE_B)   // Ahi, Alo, Whi, Wlo
#define NSTAGE    3
#define SMEM_TOTAL (SM_TILES + NSTAGE * STAGE_B)
#define SGPAD     129        // fp32 gate staging row stride

// ---------------- bf16x3 HMMA GEMM with optional fused LSTM epilogue --------
// C = A1@W1^T + A2@W2^T + bias. A row-major (M,K*), W row-major (N,K*).
// K1, K2 multiples of 64. A1 supports gather (gidx) and broadcast (lda1 = 0).
// mode 0: store C[M,N] + bias.
// mode 1: W rows are gate-interleaved (u*4+g); epilogue computes the LSTM cell
//         for units [bn/4, bn/4+32): reads c_in (null => 0), optional mask/h_old,
//         writes c_out, optional h_f32, and bf16 hi/lo h planes.
__global__ void __launch_bounds__(256, 1)
gemm_tc(float* __restrict__ C, int N,
        const __nv_bfloat16* ah1, const __nv_bfloat16* al1, int lda1,
        const int* __restrict__ gidx,
        const __nv_bfloat16* wh1, const __nv_bfloat16* wl1, int K1,
        const __nv_bfloat16* ah2, const __nv_bfloat16* al2,
        const __nv_bfloat16* wh2, const __nv_bfloat16* wl2, int K2,
        const float* __restrict__ bias,
        int mode,
        const float* __restrict__ c_in, float* __restrict__ c_out,
        float* __restrict__ h_f32,
        __nv_bfloat16* __restrict__ hh_out, __nv_bfloat16* __restrict__ hl_out,
        const float* __restrict__ maskp, const float* __restrict__ h_old)
{
    extern __shared__ char smem[];
    const uint32_t sb = smem_to_u32(smem);
    const int bm = blockIdx.y * 128, bn = blockIdx.x * 128;
    const int tid = threadIdx.x, wid = tid >> 5, lane = tid & 31;
    const int wm = (wid >> 2) * 64;          // warp tile 64 x 32
    const int wn = (wid & 3) * 32;
    int* sidx = (int*)(smem + SM_IDX);

    if (gidx && tid < 128) sidx[tid] = gidx[bm + tid];
    if (gidx) __syncthreads();

    const int nb = (K1 + K2) >> 6;
    const int use_g = (gidx != nullptr);

    auto load_stage = [&](int kb, int buf) {
        const uint32_t stage = sb + SM_TILES + buf * STAGE_B;
        #pragma unroll
        for (int j = 0; j < 4; j++) {
            int q = tid * 4 + j;                 // 0..1023
            int row = q >> 3, ch = q & 7;        // 128 rows x 8 chunks(16B)
            int kg = kb * 64 + ch * 8;
            uint32_t so = SWZ((uint32_t)(row * 128 + ch * 16));
            const __nv_bfloat16 *pah, *pal, *pwh, *pwl;
            if (kg < K1) {
                size_t ar = use_g ? (size_t)sidx[row] * lda1 : (size_t)(bm + row) * lda1;
                pah = ah1 + ar + kg;  pal = al1 + ar + kg;
                size_t wr = (size_t)(bn + row) * K1 + kg;
                pwh = wh1 + wr;       pwl = wl1 + wr;
            } else {
                int k2 = kg - K1;
                size_t ar = (size_t)(bm + row) * K2 + k2;
                pah = ah2 + ar;       pal = al2 + ar;
                size_t wr = (size_t)(bn + row) * K2 + k2;
                pwh = wh2 + wr;       pwl = wl2 + wr;
            }
            CP_ASYNC16(stage + 0 * TILE_B + so, pah);
            CP_ASYNC16(stage + 1 * TILE_B + so, pal);
            CP_ASYNC16(stage + 2 * TILE_B + so, pwh);
            CP_ASYNC16(stage + 3 * TILE_B + so, pwl);
        }
        CP_COMMIT();
    };

    float acc[4][4][4];
    #pragma unroll
    for (int mt = 0; mt < 4; mt++)
        #pragma unroll
        for (int nt = 0; nt < 4; nt++)
            #pragma unroll
            for (int i = 0; i < 4; i++) acc[mt][nt][i] = 0.f;

    load_stage(0, 0);
    load_stage(1, 1);

    for (int kb = 0; kb < nb; kb++) {
        if (kb + 1 < nb) { CP_WAIT1(); } else { CP_WAIT0(); }
        __syncthreads();
        if (kb + 2 < nb) load_stage(kb + 2, (kb + 2) % NSTAGE);
        const uint32_t stage = sb + SM_TILES + (kb % NSTAGE) * STAGE_B;

        #pragma unroll
        for (int ks = 0; ks < 4; ks++) {
            uint32_t ah[4][4], al[4][4], bh[4][2], bl[4][2];
            {
                const int arow = wm + (lane & 15);
                const int acol = ks * 32 + ((lane >> 4) << 4);
                #pragma unroll
                for (int mt = 0; mt < 4; mt++) {
                    uint32_t byte = (uint32_t)((arow + mt * 16) * 128 + acol);
                    uint32_t off = SWZ(byte);
                    LDSM4(ah[mt], stage + 0 * TILE_B + off);
                    LDSM4(al[mt], stage + 1 * TILE_B + off);
                }
            }
            {
                const int brow = wn + (lane & 7) + ((lane >> 4) << 3);
                const int bcol = ks * 32 + (((lane >> 3) & 1) << 4);
                #pragma unroll
                for (int p2 = 0; p2 < 2; p2++) {
                    uint32_t byte = (uint32_t)((brow + p2 * 16) * 128 + bcol);
                    uint32_t off = SWZ(byte);
                    uint32_t r[4];
                    LDSM4(r, stage + 2 * TILE_B + off);
                    bh[p2 * 2][0] = r[0]; bh[p2 * 2][1] = r[1];
                    bh[p2 * 2 + 1][0] = r[2]; bh[p2 * 2 + 1][1] = r[3];
                    LDSM4(r, stage + 3 * TILE_B + off);
                    bl[p2 * 2][0] = r[0]; bl[p2 * 2][1] = r[1];
                    bl[p2 * 2 + 1][0] = r[2]; bl[p2 * 2 + 1][1] = r[3];
                }
            }
            #pragma unroll
            for (int mt = 0; mt < 4; mt++)
                #pragma unroll
                for (int nt = 0; nt < 4; nt++) {
                    mma16816(acc[mt][nt], ah[mt], bh[nt]);
                    mma16816(acc[mt][nt], ah[mt], bl[nt]);
                    mma16816(acc[mt][nt], al[mt], bh[nt]);
                }
        }
    }

    if (mode == 0) {
        // ---- plain epilogue: C + bias ----
        #pragma unroll
        for (int nt = 0; nt < 4; nt++) {
            const int n0 = bn + wn + nt * 8 + 2 * (lane & 3);
            float bias0 = bias ? bias[n0] : 0.f;
            float bias1 = bias ? bias[n0 + 1] : 0.f;
            #pragma unroll
            for (int mt = 0; mt < 4; mt++) {
                const int m0 = bm + wm + mt * 16 + (lane >> 2);
                float2 v0 = make_float2(acc[mt][nt][0] + bias0, acc[mt][nt][1] + bias1);
                float2 v1 = make_float2(acc[mt][nt][2] + bias0, acc[mt][nt][3] + bias1);
                *(float2*)&C[(size_t)m0 * N + n0] = v0;
                *(float2*)&C[(size_t)(m0 + 8) * N + n0] = v1;
            }
        }
        return;
    }

    // ---- fused LSTM epilogue ----
    __syncthreads();                 // mainloop smem no longer needed
    float* sg = (float*)(smem + SM_TILES);   // [128][SGPAD]
    #pragma unroll
    for (int nt = 0; nt < 4; nt++) {
        const int ln = wn + nt * 8 + 2 * (lane & 3);
        const float bias0 = bias[bn + ln];
        const float bias1 = bias[bn + ln + 1];
        #pragma unroll
        for (int mt = 0; mt < 4; mt++) {
            const int lm = wm + mt * 16 + (lane >> 2);
            sg[lm * SGPAD + ln]           = acc[mt][nt][0] + bias0;
            sg[lm * SGPAD + ln + 1]       = acc[mt][nt][1] + bias1;
            sg[(lm + 8) * SGPAD + ln]     = acc[mt][nt][2] + bias0;
            sg[(lm + 8) * SGPAD + ln + 1] = acc[mt][nt][3] + bias1;
        }
    }
    __syncthreads();

    const int gu_base = bn >> 2;       // global unit base (32 units per CTA)
    for (int i = tid; i < 128 * 32; i += 256) {
        const int u = i & 31, m = i >> 5;
        const float* row = sg + m * SGPAD + u * 4;
        float gi_ = row[0], gf_ = row[1], gg_ = row[2], go_ = row[3];
        const int gm = bm + m;
        const size_t ci = (size_t)gm * Hd + gu_base + u;
        float cold = c_in ? c_in[ci] : 0.f;
        float si = 1.f / (1.f + expf(-gi_));
        float sf = 1.f / (1.f + expf(-gf_));
        float so = 1.f / (1.f + expf(-go_));
        float cn = sf * cold + si * tanhf(gg_);
        float hn = so * tanhf(cn);
        if (maskp) {
            float mt_ = maskp[gm];
            hn = mt_ * hn + (1.f - mt_) * h_old[ci];
            cn = mt_ * cn + (1.f - mt_) * cold;
        }
        c_out[ci] = cn;
        if (h_f32) h_f32[ci] = hn;
        __nv_bfloat16 hb = __float2bfloat16(hn);
        hh_out[ci] = hb;
        hl_out[ci] = __float2bfloat16(hn - __bfloat162float(hb));
    }
}

// ---------------- conversion kernels ----------------
__global__ void conv_split(const float* __restrict__ s, __nv_bfloat16* __restrict__ hi,
                           __nv_bfloat16* __restrict__ lo, int n)
{
    int i = blockIdx.x * blockDim.x + threadIdx.x;
    if (i >= n) return;
    float x = s[i];
    __nv_bfloat16 h = __float2bfloat16(x);
    hi[i] = h;
    lo[i] = __float2bfloat16(x - __bfloat162float(h));
}

// gate-interleaved weight conversion: dst row n' = u*4+g <- src row g*1024+u
__global__ void conv_split_perm(const float* __restrict__ s, __nv_bfloat16* __restrict__ hi,
                                __nv_bfloat16* __restrict__ lo, int K)
{
    int i = blockIdx.x * blockDim.x + threadIdx.x;
    if (i >= G4H * K) return;
    int np = i / K, k = i - np * K;
    int u = np >> 2, g = np & 3;
    float x = s[(size_t)(g * Hd + u) * K + k];
    __nv_bfloat16 h = __float2bfloat16(x);
    hi[i] = h;
    lo[i] = __float2bfloat16(x - __bfloat162float(h));
}

__global__ void prep_bias(const float* __restrict__ b1, const float* __restrict__ b2,
                          float* __restrict__ out)
{
    int np = blockIdx.x * blockDim.x + threadIdx.x;
    if (np >= G4H) return;
    int u = np >> 2, g = np & 3;
    out[np] = b1[g * Hd + u] + b2[g * Hd + u];
}

__global__ void zero_f32_bf16(float* f, __nv_bfloat16* h0, __nv_bfloat16* l0, int n)
{
    int i = blockIdx.x * blockDim.x + threadIdx.x;
    if (i >= n) return;
    if (f)  f[i] = 0.f;
    h0[i] = __float2bfloat16(0.f);
    l0[i] = __float2bfloat16(0.f);
}
__global__ void fill_val(float* p, float v, int n)
{
    int i = blockIdx.x * blockDim.x + threadIdx.x;
    if (i < n) p[i] = v;
}

// ---------------- attention + pooled representation -------------------------
__global__ void attn_r(const int* __restrict__ inp, const float* __restrict__ mask,
                       const float* __restrict__ emb, const float* __restrict__ attn_w,
                       const float* __restrict__ attn_b,
                       __nv_bfloat16* __restrict__ rh, __nv_bfloat16* __restrict__ rl)
{
    const int b = blockIdx.x;
    const int tid = threadIdx.x;
    const int lane = tid & 31, wrp = tid >> 5;
    __shared__ float aw[Wln];
    __shared__ int   idxs[Wln];
    if (tid < Wln) idxs[tid] = inp[b * Wln + tid];
    __syncthreads();
    const float* w2 = attn_w + Hd;
    for (int wi = wrp; wi < Wln; wi += 8) {
        const float* e = emb + (size_t)idxs[wi] * Hd;
        float acc = 0.f;
        for (int k = lane; k < Hd; k += 32) acc += e[k] * w2[k];
        #pragma unroll
        for (int o = 16; o; o >>= 1) acc += __shfl_xor_sync(0xffffffffu, acc, o);
        if (lane == 0) {
            float a = 1.f / (1.f + expf(-(acc + attn_b[0])));
            aw[wi] = a * mask[wi * Bsz + b];
        }
    }
    __syncthreads();
    for (int hh = tid; hh < Hd; hh += 256) {
        float acc = 0.f;
        #pragma unroll 5
        for (int wi = 0; wi < Wln; wi++)
            acc += aw[wi] * emb[(size_t)idxs[wi] * Hd + hh];
        __nv_bfloat16 hb = __float2bfloat16(acc);
        rh[b * Hd + hh] = hb;
        rl[b * Hd + hh] = __float2bfloat16(acc - __bfloat162float(hb));
    }
}

// ---------------- gen output head: GEMV + softmax + eos mask ----------------
__global__ void gen_out(const float* __restrict__ h, const float* __restrict__ outW,
                        const float* __restrict__ outb,
                        __nv_bfloat16* __restrict__ mh, __nv_bfloat16* __restrict__ ml,
                        float* __restrict__ msgmask, float* __restrict__ m_state, int l)
{
    const int b = blockIdx.x;
    const int j = threadIdx.x;                  // 64 threads
    __shared__ float4 hs4[Hd / 4];
    __shared__ float  red[2];
    const float4* hrow = (const float4*)(h + (size_t)b * Hd);
    for (int k = j; k < Hd / 4; k += 64) hs4[k] = hrow[k];
    __syncthreads();

    float acc = outb[j];
    const float4* w4 = (const float4*)(outW + (size_t)j * Hd);
    #pragma unroll 4
    for (int k = 0; k < Hd / 4; k++) {
        float4 wv = w4[k];
        float4 hv = hs4[k];
        acc += wv.x * hv.x + wv.y * hv.y + wv.z * hv.z + wv.w * hv.w;
    }
    float vmax = acc;
    #pragma unroll
    for (int o = 16; o; o >>= 1) vmax = fmaxf(vmax, __shfl_xor_sync(0xffffffffu, vmax, o));
    if ((j & 31) == 0) red[j >> 5] = vmax;
    __syncthreads();
    vmax = fmaxf(red[0], red[1]);
    float e = expf(acc - vmax);
    float s = e;
    #pragma unroll
    for (int o = 16; o; o >>= 1) s += __shfl_xor_sync(0xffffffffu, s, o);
    __syncthreads();
    if ((j & 31) == 0) red[j >> 5] = s;
    __syncthreads();
    s = red[0] + red[1];
    float p = e / s;
    size_t oi = (size_t)l * Bsz * MVd + b * MVd + j;
    __nv_bfloat16 pb = __float2bfloat16(p);
    mh[oi] = pb;
    ml[oi] = __float2bfloat16(p - __bfloat162float(pb));
    if (j == EOS_INDEX) {
        float mo = m_state[b];
        msgmask[l * Bsz + b] = mo;
        m_state[b] = mo * (1.f - p);
    }
}

// ---------------- host orchestration ----------------
extern "C" void kernel_launch(void* const* d_in, const int* in_sizes, int n_in,
                              void* d_out, int out_size)
{
    const int s = (in_sizes[3] == 1) ? 1 : 0;

    const int*   input_var  = (const int*)  d_in[0];
    const float* input_mask = (const float*)d_in[1];
    const int*   target_var = (const int*)  d_in[2];
    const float* embedding  = (const float*)d_in[3 + s];
    const float* attn_w     = (const float*)d_in[4 + s];
    const float* attn_b     = (const float*)d_in[5 + s];
    const float* set_Wih    = (const float*)d_in[6 + s];
    const float* set_bih    = (const float*)d_in[8 + s];
    const float* set_bhh    = (const float*)d_in[9 + s];
    const float* gen_Whh    = (const float*)d_in[14 + s];
    const float* gen_bih    = (const float*)d_in[15 + s];
    const float* gen_bhh    = (const float*)d_in[16 + s];
    const float* gen_outW   = (const float*)d_in[17 + s];
    const float* gen_outb   = (const float*)d_in[18 + s];
    const float* menc_Wih   = (const float*)d_in[19 + s];
    const float* menc_Whh   = (const float*)d_in[20 + s];
    const float* menc_bih   = (const float*)d_in[21 + s];
    const float* menc_bhh   = (const float*)d_in[22 + s];
    const float* dec_Wih    = (const float*)d_in[25 + s];
    const float* dec_Whh    = (const float*)d_in[26 + s];
    const float* dec_bih    = (const float*)d_in[27 + s];
    const float* dec_bhh    = (const float*)d_in[28 + s];
    const float* dec_outW   = (const float*)d_in[29 + s];
    const float* dec_outb   = (const float*)d_in[30 + s];
    float* out = (float*)d_out;

    float *c, *mm, *m, *hA32, *hB32;
    cudaGetSymbolAddress((void**)&c,    d_c);
    cudaGetSymbolAddress((void**)&mm,   d_mm);
    cudaGetSymbolAddress((void**)&m,    d_m);
    cudaGetSymbolAddress((void**)&hA32, d_hA32);
    cudaGetSymbolAddress((void**)&hB32, d_hB32);
    __nv_bfloat16 *ehi, *elo, *wsh, *wsl, *wgh, *wgl, *wmih, *wmil, *wmhh, *wmhl;
    __nv_bfloat16 *wdih, *wdil, *wdhh, *wdhl, *woh, *wol;
    __nv_bfloat16 *hAh, *hAl, *hBh, *hBl, *rh, *rl, *msh, *msl, *hah, *hal;
    float *pbs, *pbg, *pbm, *pbd;
    cudaGetSymbolAddress((void**)&ehi, e_hi);    cudaGetSymbolAddress((void**)&elo, e_lo);
    cudaGetSymbolAddress((void**)&wsh, wset_h);  cudaGetSymbolAddress((void**)&wsl, wset_l);
    cudaGetSymbolAddress((void**)&wgh, wgen_h);  cudaGetSymbolAddress((void**)&wgl, wgen_l);
    cudaGetSymbolAddress((void**)&wmih, wmi_h);  cudaGetSymbolAddress((void**)&wmil, wmi_l);
    cudaGetSymbolAddress((void**)&wmhh, wmh_h);  cudaGetSymbolAddress((void**)&wmhl, wmh_l);
    cudaGetSymbolAddress((void**)&wdih, wdi_h);  cudaGetSymbolAddress((void**)&wdil, wdi_l);
    cudaGetSymbolAddress((void**)&wdhh, wdh_h);  cudaGetSymbolAddress((void**)&wdhl, wdh_l);
    cudaGetSymbolAddress((void**)&woh, wo_h);    cudaGetSymbolAddress((void**)&wol, wo_l);
    cudaGetSymbolAddress((void**)&hAh, hA_hi);   cudaGetSymbolAddress((void**)&hAl, hA_lo);
    cudaGetSymbolAddress((void**)&hBh, hB_hi);   cudaGetSymbolAddress((void**)&hBl, hB_lo);
    cudaGetSymbolAddress((void**)&rh,  r_hi);    cudaGetSymbolAddress((void**)&rl,  r_lo);
    cudaGetSymbolAddress((void**)&msh, msg_hi);  cudaGetSymbolAddress((void**)&msl, msg_lo);
    cudaGetSymbolAddress((void**)&hah, hall_hi); cudaGetSymbolAddress((void**)&hal, hall_lo);
    cudaGetSymbolAddress((void**)&pbs, pb_set);  cudaGetSymbolAddress((void**)&pbg, pb_gen);
    cudaGetSymbolAddress((void**)&pbm, pb_menc); cudaGetSymbolAddress((void**)&pbd, pb_dec);

    cudaFuncSetAttribute(gemm_tc, cudaFuncAttributeMaxDynamicSharedMemorySize, SMEM_TOTAL);

    const dim3 rg(G4H / 128, Bsz / 128);         // (32, 4)
    const int  cb = (Bsz * Hd) / 256;

    // 0) operand conversion (once per launch)
    conv_split<<<(Vb * Hd + 255) / 256, 256>>>(embedding, ehi, elo, Vb * Hd);
    conv_split<<<(Vb * Hd + 255) / 256, 256>>>(dec_outW, woh, wol, Vb * Hd);
    conv_split_perm<<<(G4H * Hd + 255) / 256, 256>>>(set_Wih,  wsh,  wsl,  Hd);
    conv_split_perm<<<(G4H * Hd + 255) / 256, 256>>>(gen_Whh,  wgh,  wgl,  Hd);
    conv_split_perm<<<(G4H * MVd + 255) / 256, 256>>>(menc_Wih, wmih, wmil, MVd);
    conv_split_perm<<<(G4H * Hd + 255) / 256, 256>>>(menc_Whh, wmhh, wmhl, Hd);
    conv_split_perm<<<(G4H * Hd + 255) / 256, 256>>>(dec_Wih,  wdih, wdil, Hd);
    conv_split_perm<<<(G4H * Hd + 255) / 256, 256>>>(dec_Whh,  wdhh, wdhl, Hd);
    prep_bias<<<G4H / 256, 256>>>(set_bih,  set_bhh,  pbs);
    prep_bias<<<G4H / 256, 256>>>(gen_bih,  gen_bhh,  pbg);
    prep_bias<<<G4H / 256, 256>>>(menc_bih, menc_bhh, pbm);
    prep_bias<<<G4H / 256, 256>>>(dec_bih,  dec_bhh,  pbd);

    // 1) attention + pooled r
    attn_r<<<Bsz, 256>>>(input_var, input_mask, embedding, attn_w, attn_b, rh, rl);

    // 2) set encoder cell (h0 = c0 = 0) -> writes hA (f32 + hi/lo) and c
    gemm_tc<<<rg, 256, SMEM_TOTAL>>>(nullptr, G4H, rh, rl, Hd, nullptr, wsh, wsl, Hd,
                                     nullptr, nullptr, nullptr, nullptr, 0, pbs,
                                     1, nullptr, c, hA32, hAh, hAl, nullptr, nullptr);

    // 3) gen loop (x == 0 -> only h@Whh); ping-pong h buffers
    fill_val<<<2, 256>>>(m, 1.f, Bsz);
    {
        __nv_bfloat16 *ph = hAh, *pl = hAl, *qh = hBh, *ql = hBl;
        float *pf = hA32, *qf = hB32;
        for (int l = 0; l < Ld; l++) {
            gemm_tc<<<rg, 256, SMEM_TOTAL>>>(nullptr, G4H,
                                             nullptr, nullptr, 0, nullptr,
                                             nullptr, nullptr, 0,
                                             ph, pl, wgh, wgl, Hd, pbg,
                                             1, c, c, qf, qh, ql, nullptr, nullptr);
            gen_out<<<Bsz, 64>>>(qf, gen_outW, gen_outb, msh, msl, mm, m, l);
            { __nv_bfloat16* t; t = ph; ph = qh; qh = t; t = pl; pl = ql; ql = t; }
            { float* t = pf; pf = qf; qf = t; }
        }
    }

    // 4) message encoder loop (h0 = c0 = 0); masked update needs h_old f32
    zero_f32_bf16<<<cb, 256>>>(hA32, hAh, hAl, Bsz * Hd);
    fill_val<<<cb, 256>>>(c, 0.f, Bsz * Hd);
    {
        __nv_bfloat16 *ph = hAh, *pl = hAl, *qh = hBh, *ql = hBl;
        float *pf = hA32, *qf = hB32;
        for (int l = 0; l < Ld; l++) {
            gemm_tc<<<rg, 256, SMEM_TOTAL>>>(nullptr, G4H,
                                             msh + (size_t)l * Bsz * MVd,
                                             msl + (size_t)l * Bsz * MVd, MVd, nullptr,
                                             wmih, wmil, MVd,
                                             ph, pl, wmhh, wmhl, Hd, pbm,
                                             1, c, c, qf, qh, ql, mm + l * Bsz, pf);
            { __nv_bfloat16* t; t = ph; ph = qh; qh = t; t = pl; pl = ql; ql = t; }
            { float* t = pf; pf = qf; qf = t; }
        }
        // after loop: final menc h is in ph/pl (last written)
        if (((Ld) & 1) == 0) { /* even # of swaps -> back to hA */ }
        // dec t=0 uses ph/pl captured below via explicit pointers:
        // store them by re-launching dec loop with these pointers
        // (handled: Ld=30 even -> final is hA buffers)
    }

    // 5) decoder loop: fused [x;h] GEMM; h -> hall hi/lo ring, c carried
    // Ld=30 even -> menc final h is in hA buffers.
    for (int t = 0; t < Tln; t++) {
        const __nv_bfloat16* A1h = ehi + (size_t)SOS_INDEX * Hd;
        const __nv_bfloat16* A1l = elo + (size_t)SOS_INDEX * Hd;
        int        lda1 = (t == 0) ? 0 : Hd;
        const int* gi   = (t == 0) ? nullptr : (target_var + (size_t)(t - 1) * Bsz);
        const __nv_bfloat16* A2h = (t == 0) ? hAh : (hah + (size_t)(t - 1) * Bsz * Hd);
        const __nv_bfloat16* A2l = (t == 0) ? hAl : (hal + (size_t)(t - 1) * Bsz * Hd);
        gemm_tc<<<rg, 256, SMEM_TOTAL>>>(nullptr, G4H, (t == 0) ? A1h : ehi,
                                         (t == 0) ? A1l : elo, lda1, gi,
                                         wdih, wdil, Hd,
                                         A2h, A2l, wdhh, wdhl, Hd, pbd,
                                         1, c, c, nullptr,
                                         hah + (size_t)t * Bsz * Hd,
                                         hal + (size_t)t * Bsz * Hd,
                                         nullptr, nullptr);
    }

    // 6) batched logits: (T*B, H) @ (V, H)^T + b -> d_out
    gemm_tc<<<dim3(Vb / 128, (Tln * Bsz) / 128), 256, SMEM_TOTAL>>>(
        out, Vb, nullptr, nullptr, 0, nullptr, nullptr, nullptr, 0,
        hah, hal, woh, wol, Hd, dec_outb,
        0, nullptr, nullptr, nullptr, nullptr, nullptr, nullptr, nullptr);
}